// round 1
// baseline (speedup 1.0000x reference)
#include <cuda_runtime.h>
#include <math.h>

#define B_ROWS 32768
#define C_CLS  1000

// scratch for per-row losses (no device allocation allowed)
__device__ float g_row_loss[B_ROWS];

// ---------------------------------------------------------------------------
// Kernel 1: one warp per row. 32 elements per lane in registers.
//   u[k] = -0.2 * (x - mu)  (>= 0; masked slots = +inf -> contribute 0)
//   iterate s: Z = sum (1 + u*s)^-5 ; s = Z^-0.2   (5 times)
//   final Zf with s; zp = Zf^0.2 ; r_f = u + zp ; p = r_f^-5
//   L = A - B/r_f + (1/1.2) * r_f^-6  (A,B per-class constants, on/off)
//   row_loss = sum_c weight[c] * L_c
// ---------------------------------------------------------------------------
__global__ __launch_bounds__(256)
void bitempered_row_kernel(const float* __restrict__ logits,
                           const int*   __restrict__ truth,
                           const float* __restrict__ weight,
                           float A_on, float A_off,
                           float B_on, float B_off)
{
    const int lane = threadIdx.x & 31;
    const int wib  = threadIdx.x >> 5;
    const int row  = blockIdx.x * 8 + wib;
    if (row >= B_ROWS) return;

    const float4* xrow = (const float4*)(logits + (size_t)row * C_CLS);

    float u[32];
    float xmax = -INFINITY;
    #pragma unroll
    for (int j = 0; j < 8; ++j) {
        const int q = lane + 32 * j;            // float4 index, valid iff q < 250
        float4 v;
        if (q < 250) v = xrow[q];
        else         v = make_float4(-INFINITY, -INFINITY, -INFINITY, -INFINITY);
        u[4*j+0] = v.x; u[4*j+1] = v.y; u[4*j+2] = v.z; u[4*j+3] = v.w;
        xmax = fmaxf(xmax, fmaxf(fmaxf(v.x, v.y), fmaxf(v.z, v.w)));
    }
    #pragma unroll
    for (int o = 16; o; o >>= 1)
        xmax = fmaxf(xmax, __shfl_xor_sync(0xffffffffu, xmax, o));

    // u = -0.2*(x - mu); invalid slots: -0.2*(-inf) = +inf
    #pragma unroll
    for (int k = 0; k < 32; ++k)
        u[k] = -0.2f * (u[k] - xmax);

    // 5 fixed-point iterations on the scalar s = Z^{-0.2}
    float s = 1.0f;
    #pragma unroll
    for (int it = 0; it < 5; ++it) {
        float z = 0.0f;
        #pragma unroll
        for (int k = 0; k < 32; ++k) {
            float r   = fmaf(u[k], s, 1.0f);   // >= 1 (inf for masked)
            float inv = 1.0f / r;              // 0 for masked
            float i2  = inv * inv;
            z += i2 * i2 * inv;                // r^-5
        }
        #pragma unroll
        for (int o = 16; o; o >>= 1)
            z += __shfl_xor_sync(0xffffffffu, z, o);
        s = powf(z, -0.2f);
    }

    // final partition with converged s
    float zf = 0.0f;
    #pragma unroll
    for (int k = 0; k < 32; ++k) {
        float r   = fmaf(u[k], s, 1.0f);
        float inv = 1.0f / r;
        float i2  = inv * inv;
        zf += i2 * i2 * inv;
    }
    #pragma unroll
    for (int o = 16; o; o >>= 1)
        zf += __shfl_xor_sync(0xffffffffu, zf, o);

    const float zp = powf(zf, 0.2f);   // r_f = u + zp  (== 1 - 0.2*(x - nc))
    const int   t  = truth[row];

    const float4* w4 = (const float4*)weight;
    float acc = 0.0f;
    #pragma unroll
    for (int j = 0; j < 8; ++j) {
        const int q = lane + 32 * j;
        if (q < 250) {
            float4 wv = w4[q];
            float wk[4] = { wv.x, wv.y, wv.z, wv.w };
            #pragma unroll
            for (int kk = 0; kk < 4; ++kk) {
                const int   c   = 4 * q + kk;
                const int   k   = 4 * j + kk;
                const float r   = u[k] + zp;        // >= 1
                const float inv = 1.0f / r;         // = p^{0.2}
                const float i2  = inv * inv;
                const float p5  = i2 * i2 * inv;    // p
                const float p12 = p5 * inv;         // p^{1.2}
                const bool  on  = (c == t);
                const float A   = on ? A_on : A_off;   // Cy + 5y
                const float Bc  = on ? B_on : B_off;   // 5y
                const float L   = fmaf(p12, (1.0f / 1.2f), fmaf(-Bc, inv, A));
                acc = fmaf(wk[kk], L, acc);
            }
        }
    }
    #pragma unroll
    for (int o = 16; o; o >>= 1)
        acc += __shfl_xor_sync(0xffffffffu, acc, o);

    if (lane == 0) g_row_loss[row] = acc;
}

// ---------------------------------------------------------------------------
// Kernel 2: reduce row losses + weight sum, write mean scalar.
// ---------------------------------------------------------------------------
__global__ __launch_bounds__(1024)
void bitempered_reduce_kernel(const float* __restrict__ weight,
                              float* __restrict__ out)
{
    __shared__ float sm[32];
    const int tid  = threadIdx.x;
    const int lane = tid & 31;
    const int w    = tid >> 5;

    // sum of weights
    float ws = 0.0f;
    for (int c = tid; c < C_CLS; c += 1024) ws += weight[c];
    #pragma unroll
    for (int o = 16; o; o >>= 1) ws += __shfl_xor_sync(0xffffffffu, ws, o);
    if (lane == 0) sm[w] = ws;
    __syncthreads();
    float wsum = 0.0f;
    if (w == 0) {
        wsum = sm[lane];
        #pragma unroll
        for (int o = 16; o; o >>= 1) wsum += __shfl_xor_sync(0xffffffffu, wsum, o);
    }
    __syncthreads();

    // sum of row losses
    float ls = 0.0f;
    for (int i = tid; i < B_ROWS; i += 1024) ls += g_row_loss[i];
    #pragma unroll
    for (int o = 16; o; o >>= 1) ls += __shfl_xor_sync(0xffffffffu, ls, o);
    if (lane == 0) sm[w] = ls;
    __syncthreads();
    if (tid == 0) {
        float lsum = 0.0f;
        #pragma unroll
        for (int i = 0; i < 32; ++i) lsum += sm[i];
        out[0] = lsum * ((float)C_CLS / wsum) * (1.0f / (float)B_ROWS);
    }
}

// ---------------------------------------------------------------------------
extern "C" void kernel_launch(void* const* d_in, const int* in_sizes, int n_in,
                              void* d_out, int out_size)
{
    const float* logits = (const float*)d_in[0];
    const int*   truth  = (const int*)  d_in[1];
    const float* weight = (const float*)d_in[2];
    float* out = (float*)d_out;

    // host-side per-class constants (double precision)
    const double T1 = 0.8, SM = 0.05;
    const double Cd = (double)C_CLS;
    const double y_on  = (1.0 - SM * Cd / (Cd - 1.0)) + SM / (Cd - 1.0);
    const double y_off = SM / (Cd - 1.0);
    auto logt1 = [](double v) { return (pow(v, 0.2) - 1.0) / 0.2; };
    auto Cy = [&](double y) {
        return y * logt1(y + 1e-10) - pow(y, 2.0 - T1) / (2.0 - T1);
    };
    const float A_on  = (float)(Cy(y_on)  + 5.0 * y_on);
    const float A_off = (float)(Cy(y_off) + 5.0 * y_off);
    const float B_on  = (float)(5.0 * y_on);
    const float B_off = (float)(5.0 * y_off);

    bitempered_row_kernel<<<B_ROWS / 8, 256>>>(logits, truth, weight,
                                               A_on, A_off, B_on, B_off);
    bitempered_reduce_kernel<<<1, 1024>>>(weight, out);
}

// round 2
// speedup vs baseline: 1.7028x; 1.7028x over previous
#include <cuda_runtime.h>
#include <math.h>

#define B_ROWS 32768
#define C_CLS  1000
#define NBLK   (B_ROWS / 8)

// scratch: per-block partial losses (no device allocation allowed)
__device__ float g_blk_loss[NBLK];

__device__ __forceinline__ float frcp(float x) {
    float r; asm("rcp.approx.f32 %0, %1;" : "=f"(r) : "f"(x)); return r;
}
__device__ __forceinline__ float fpow_fast(float x, float p) {
    float lg; asm("lg2.approx.f32 %0, %1;" : "=f"(lg) : "f"(x));
    float e = lg * p;
    float r; asm("ex2.approx.f32 %0, %1;" : "=f"(r) : "f"(e)); return r;
}

// ---------------------------------------------------------------------------
// Kernel 1: one warp per row, 32 elems/lane in registers.
//   u = -0.2*(x - mu) >= 0 (masked slots +inf -> contribute 0)
//   5x: Z = sum (1 + u*s)^-5 ; s = Z^-0.2
//   zp = Zf^0.2 ; r_f = u + zp ; inv = 1/r_f (= p^0.2)
//   L = A - B*inv + (1/1.2) * inv^6 ; row_loss = sum_c w_c * L_c
//   block accumulates its 8 row losses -> g_blk_loss[blockIdx.x]
// ---------------------------------------------------------------------------
__global__ __launch_bounds__(256)
void bitempered_row_kernel(const float* __restrict__ logits,
                           const int*   __restrict__ truth,
                           const float* __restrict__ weight,
                           float A_on, float A_off,
                           float B_on, float B_off)
{
    __shared__ float sm[8];
    const int lane = threadIdx.x & 31;
    const int wib  = threadIdx.x >> 5;
    const int row  = blockIdx.x * 8 + wib;

    const float4* xrow = (const float4*)(logits + (size_t)row * C_CLS);

    float u[32];
    float xmax = -INFINITY;
    #pragma unroll
    for (int j = 0; j < 8; ++j) {
        const int q = lane + 32 * j;            // float4 index, valid iff q < 250
        float4 v;
        if (q < 250) v = xrow[q];
        else         v = make_float4(-INFINITY, -INFINITY, -INFINITY, -INFINITY);
        u[4*j+0] = v.x; u[4*j+1] = v.y; u[4*j+2] = v.z; u[4*j+3] = v.w;
        xmax = fmaxf(xmax, fmaxf(fmaxf(v.x, v.y), fmaxf(v.z, v.w)));
    }
    #pragma unroll
    for (int o = 16; o; o >>= 1)
        xmax = fmaxf(xmax, __shfl_xor_sync(0xffffffffu, xmax, o));

    // u = -0.2*(x - mu); invalid slots: -0.2*(-inf) = +inf
    #pragma unroll
    for (int k = 0; k < 32; ++k)
        u[k] = -0.2f * (u[k] - xmax);

    // 5 fixed-point iterations on the scalar s = Z^{-0.2}
    float s = 1.0f;
    #pragma unroll
    for (int it = 0; it < 5; ++it) {
        float z = 0.0f;
        #pragma unroll
        for (int k = 0; k < 32; ++k) {
            float r   = fmaf(u[k], s, 1.0f);   // >= 1 (inf for masked)
            float inv = frcp(r);               // 0 for masked
            float i2  = inv * inv;
            z = fmaf(i2 * i2, inv, z);         // += r^-5
        }
        #pragma unroll
        for (int o = 16; o; o >>= 1)
            z += __shfl_xor_sync(0xffffffffu, z, o);
        s = fpow_fast(z, -0.2f);
    }

    // final partition with converged s
    float zf = 0.0f;
    #pragma unroll
    for (int k = 0; k < 32; ++k) {
        float r   = fmaf(u[k], s, 1.0f);
        float inv = frcp(r);
        float i2  = inv * inv;
        zf = fmaf(i2 * i2, inv, zf);
    }
    #pragma unroll
    for (int o = 16; o; o >>= 1)
        zf += __shfl_xor_sync(0xffffffffu, zf, o);

    const float zp = fpow_fast(zf, 0.2f);   // r_f = u + zp == 1 - 0.2*(x - nc)
    const int   t  = truth[row];

    const float4* w4 = (const float4*)weight;
    float acc = 0.0f;
    #pragma unroll
    for (int j = 0; j < 8; ++j) {
        const int q = lane + 32 * j;
        if (q < 250) {
            float4 wv = w4[q];
            float wk[4] = { wv.x, wv.y, wv.z, wv.w };
            #pragma unroll
            for (int kk = 0; kk < 4; ++kk) {
                const int   c   = 4 * q + kk;
                const int   k   = 4 * j + kk;
                const float r   = u[k] + zp;        // >= 1
                const float inv = frcp(r);          // = p^{0.2}
                const float i2  = inv * inv;
                const float i4  = i2 * i2;
                const float p12 = i4 * i2;          // p^{1.2}
                const bool  on  = (c == t);
                const float A   = on ? A_on : A_off;   // Cy + 5y
                const float Bc  = on ? B_on : B_off;   // 5y
                const float L   = fmaf(p12, (1.0f / 1.2f), fmaf(-Bc, inv, A));
                acc = fmaf(wk[kk], L, acc);
            }
        }
    }
    #pragma unroll
    for (int o = 16; o; o >>= 1)
        acc += __shfl_xor_sync(0xffffffffu, acc, o);

    if (lane == 0) sm[wib] = acc;
    __syncthreads();
    if (threadIdx.x == 0) {
        float bs = 0.0f;
        #pragma unroll
        for (int i = 0; i < 8; ++i) bs += sm[i];
        g_blk_loss[blockIdx.x] = bs;
    }
}

// ---------------------------------------------------------------------------
// Kernel 2: reduce block partials + weight sum, write mean scalar.
// ---------------------------------------------------------------------------
__global__ __launch_bounds__(1024)
void bitempered_reduce_kernel(const float* __restrict__ weight,
                              float* __restrict__ out)
{
    __shared__ float sm[32];
    const int tid  = threadIdx.x;
    const int lane = tid & 31;
    const int w    = tid >> 5;

    // sum of weights
    float ws = (tid < C_CLS) ? weight[tid] : 0.0f;
    #pragma unroll
    for (int o = 16; o; o >>= 1) ws += __shfl_xor_sync(0xffffffffu, ws, o);
    if (lane == 0) sm[w] = ws;
    __syncthreads();
    float wsum = 0.0f;
    if (tid == 0) {
        #pragma unroll
        for (int i = 0; i < 32; ++i) wsum += sm[i];
    }
    __syncthreads();

    // sum of block partials (4096 = 1024*4)
    float ls = 0.0f;
    #pragma unroll
    for (int i = 0; i < NBLK / 1024; ++i) ls += g_blk_loss[tid + i * 1024];
    #pragma unroll
    for (int o = 16; o; o >>= 1) ls += __shfl_xor_sync(0xffffffffu, ls, o);
    if (lane == 0) sm[w] = ls;
    __syncthreads();
    if (tid == 0) {
        float lsum = 0.0f;
        #pragma unroll
        for (int i = 0; i < 32; ++i) lsum += sm[i];
        out[0] = lsum * ((float)C_CLS / wsum) * (1.0f / (float)B_ROWS);
    }
}

// ---------------------------------------------------------------------------
extern "C" void kernel_launch(void* const* d_in, const int* in_sizes, int n_in,
                              void* d_out, int out_size)
{
    const float* logits = (const float*)d_in[0];
    const int*   truth  = (const int*)  d_in[1];
    const float* weight = (const float*)d_in[2];
    float* out = (float*)d_out;

    // host-side per-class constants (double precision)
    const double T1 = 0.8, SM = 0.05;
    const double Cd = (double)C_CLS;
    const double y_on  = (1.0 - SM * Cd / (Cd - 1.0)) + SM / (Cd - 1.0);
    const double y_off = SM / (Cd - 1.0);
    auto logt1 = [](double v) { return (pow(v, 0.2) - 1.0) / 0.2; };
    auto Cy = [&](double y) {
        return y * logt1(y + 1e-10) - pow(y, 2.0 - T1) / (2.0 - T1);
    };
    const float A_on  = (float)(Cy(y_on)  + 5.0 * y_on);
    const float A_off = (float)(Cy(y_off) + 5.0 * y_off);
    const float B_on  = (float)(5.0 * y_on);
    const float B_off = (float)(5.0 * y_off);

    bitempered_row_kernel<<<NBLK, 256>>>(logits, truth, weight,
                                         A_on, A_off, B_on, B_off);
    bitempered_reduce_kernel<<<1, 1024>>>(weight, out);
}

// round 3
// speedup vs baseline: 2.0499x; 1.2039x over previous
#include <cuda_runtime.h>
#include <math.h>

#define B_ROWS 32768
#define C_CLS  1000
#define NBLK   (B_ROWS / 8)

__device__ float g_blk_loss[NBLK];

typedef unsigned long long u64;

__device__ __forceinline__ float frcp(float x) {
    float r; asm("rcp.approx.f32 %0, %1;" : "=f"(r) : "f"(x)); return r;
}
__device__ __forceinline__ float fpow_fast(float x, float p) {
    float lg; asm("lg2.approx.f32 %0, %1;" : "=f"(lg) : "f"(x));
    float e = lg * p;
    float r; asm("ex2.approx.f32 %0, %1;" : "=f"(r) : "f"(e)); return r;
}
__device__ __forceinline__ u64 pk(float x, float y) {
    u64 r; asm("mov.b64 %0, {%1,%2};" : "=l"(r) : "f"(x), "f"(y)); return r;
}
__device__ __forceinline__ void upk(u64 v, float& x, float& y) {
    asm("mov.b64 {%0,%1}, %2;" : "=f"(x), "=f"(y) : "l"(v));
}
__device__ __forceinline__ u64 fma2(u64 a, u64 b, u64 c) {
    u64 d; asm("fma.rn.f32x2 %0, %1, %2, %3;" : "=l"(d) : "l"(a), "l"(b), "l"(c)); return d;
}
__device__ __forceinline__ u64 mul2(u64 a, u64 b) {
    u64 d; asm("mul.rn.f32x2 %0, %1, %2;" : "=l"(d) : "l"(a), "l"(b)); return d;
}
__device__ __forceinline__ u64 add2(u64 a, u64 b) {
    u64 d; asm("add.rn.f32x2 %0, %1, %2;" : "=l"(d) : "l"(a), "l"(b)); return d;
}
// rcp both halves of a packed pair (2x MUFU)
__device__ __forceinline__ u64 rcp2(u64 v) {
    float x, y; upk(v, x, y);
    return pk(frcp(x), frcp(y));
}

// ---------------------------------------------------------------------------
// Kernel 1: one warp per row; 32 elems/lane held as 16 packed f32x2 regs.
//   u = -0.2*(x - mu) >= 0 (masked slots: raw -inf -> u = +inf -> rcp -> 0)
//   6 passes: Z = sum (1 + u*s)^-5 ; first 5 update s = Z^-0.2
//   zp = Zf^0.2 ; inv = 1/(u + zp) (= p^0.2)
//   L_off = A_off - B_off*inv + (1/1.2)*inv^6   (uniform, packed)
//   truth-class correction applied as scalar on lane 0.
// ---------------------------------------------------------------------------
__global__ __launch_bounds__(256)
void bitempered_row_kernel(const float* __restrict__ logits,
                           const int*   __restrict__ truth,
                           const float* __restrict__ weight,
                           float A_off, float B_off, float dA, float dB)
{
    __shared__ float sm[8];
    const int lane = threadIdx.x & 31;
    const int wib  = threadIdx.x >> 5;
    const int row  = blockIdx.x * 8 + wib;

    const int   t  = truth[row];                       // uniform per warp
    const float xt = logits[(size_t)row * C_CLS + t];  // truth-class logit
    const float wt = __ldg(weight + t);

    const float4* xrow = (const float4*)(logits + (size_t)row * C_CLS);

    u64 u2[16];
    float xmax = -INFINITY;
    #pragma unroll
    for (int j = 0; j < 8; ++j) {
        const int q = lane + 32 * j;            // float4 index, valid iff q < 250
        float4 v;
        if (q < 250) v = xrow[q];
        else         v = make_float4(-INFINITY, -INFINITY, -INFINITY, -INFINITY);
        u2[2*j]   = pk(v.x, v.y);
        u2[2*j+1] = pk(v.z, v.w);
        xmax = fmaxf(xmax, fmaxf(fmaxf(v.x, v.y), fmaxf(v.z, v.w)));
    }
    #pragma unroll
    for (int o = 16; o; o >>= 1)
        xmax = fmaxf(xmax, __shfl_xor_sync(0xffffffffu, xmax, o));

    // u = fma(x, -0.2, 0.2*xmax); masked raw -inf -> +inf
    {
        const u64 cm = pk(-0.2f, -0.2f);
        const u64 ca = pk(0.2f * xmax, 0.2f * xmax);
        #pragma unroll
        for (int i = 0; i < 16; ++i)
            u2[i] = fma2(u2[i], cm, ca);
    }

    const u64 ONE2 = pk(1.0f, 1.0f);

    // 5 fixed-point updates of s = Z^-0.2, then final Zf with converged s
    float s  = 1.0f;
    float zf = 0.0f;
    #pragma unroll
    for (int it = 0; it < 6; ++it) {
        const u64 s2 = pk(s, s);
        u64 z2 = pk(0.0f, 0.0f);
        #pragma unroll
        for (int i = 0; i < 16; ++i) {
            u64 r2   = fma2(u2[i], s2, ONE2);  // >= 1 (inf for masked)
            u64 inv2 = rcp2(r2);               // 0 for masked
            u64 q2   = mul2(inv2, inv2);
            u64 q4   = mul2(q2, q2);
            z2 = fma2(q4, inv2, z2);           // += r^-5
        }
        float zx, zy; upk(z2, zx, zy);
        float z = zx + zy;
        #pragma unroll
        for (int o = 16; o; o >>= 1)
            z += __shfl_xor_sync(0xffffffffu, z, o);
        if (it < 5) s = fpow_fast(z, -0.2f);
        else        zf = z;
    }

    const float zp  = fpow_fast(zf, 0.2f);   // r_f = u + zp == 1 - 0.2*(x - nc)
    const u64   zp2 = pk(zp, zp);
    const u64   A2  = pk(A_off, A_off);
    const u64   nB2 = pk(-B_off, -B_off);
    const u64   C2  = pk(1.0f / 1.2f, 1.0f / 1.2f);

    const float4* w4 = (const float4*)weight;
    u64 acc2 = pk(0.0f, 0.0f);
    #pragma unroll
    for (int j = 0; j < 8; ++j) {
        const int q = lane + 32 * j;
        if (q < 250) {
            float4 wv = w4[q];
            u64 w2[2] = { pk(wv.x, wv.y), pk(wv.z, wv.w) };
            #pragma unroll
            for (int h = 0; h < 2; ++h) {
                u64 r2   = add2(u2[2*j + h], zp2);   // >= 1
                u64 inv2 = rcp2(r2);                 // = p^{0.2}
                u64 q2   = mul2(inv2, inv2);
                u64 q4   = mul2(q2, q2);
                u64 p12  = mul2(q4, q2);             // p^{1.2}
                u64 t2   = fma2(inv2, nB2, A2);      // A_off - B_off*inv
                u64 L2   = fma2(p12, C2, t2);
                acc2 = fma2(w2[h], L2, acc2);
            }
        }
    }
    float ax, ay; upk(acc2, ax, ay);
    float acc = ax + ay;
    #pragma unroll
    for (int o = 16; o; o >>= 1)
        acc += __shfl_xor_sync(0xffffffffu, acc, o);

    if (lane == 0) {
        // truth-class correction: + w[t] * (dA - dB * inv_t)
        const float ut   = fmaf(xt, -0.2f, 0.2f * xmax);
        const float invt = frcp(ut + zp);
        acc += wt * fmaf(-dB, invt, dA);
        sm[wib] = acc;
    }
    __syncthreads();
    if (threadIdx.x == 0) {
        float bs = 0.0f;
        #pragma unroll
        for (int i = 0; i < 8; ++i) bs += sm[i];
        g_blk_loss[blockIdx.x] = bs;
    }
}

// ---------------------------------------------------------------------------
// Kernel 2: reduce block partials + weight sum, write mean scalar.
// ---------------------------------------------------------------------------
__global__ __launch_bounds__(1024)
void bitempered_reduce_kernel(const float* __restrict__ weight,
                              float* __restrict__ out)
{
    __shared__ float sm[32];
    const int tid  = threadIdx.x;
    const int lane = tid & 31;
    const int w    = tid >> 5;

    float ws = (tid < C_CLS) ? weight[tid] : 0.0f;
    #pragma unroll
    for (int o = 16; o; o >>= 1) ws += __shfl_xor_sync(0xffffffffu, ws, o);
    if (lane == 0) sm[w] = ws;
    __syncthreads();
    float wsum = 0.0f;
    if (tid == 0) {
        #pragma unroll
        for (int i = 0; i < 32; ++i) wsum += sm[i];
    }
    __syncthreads();

    float ls = 0.0f;
    #pragma unroll
    for (int i = 0; i < NBLK / 1024; ++i) ls += g_blk_loss[tid + i * 1024];
    #pragma unroll
    for (int o = 16; o; o >>= 1) ls += __shfl_xor_sync(0xffffffffu, ls, o);
    if (lane == 0) sm[w] = ls;
    __syncthreads();
    if (tid == 0) {
        float lsum = 0.0f;
        #pragma unroll
        for (int i = 0; i < 32; ++i) lsum += sm[i];
        out[0] = lsum * ((float)C_CLS / wsum) * (1.0f / (float)B_ROWS);
    }
}

// ---------------------------------------------------------------------------
extern "C" void kernel_launch(void* const* d_in, const int* in_sizes, int n_in,
                              void* d_out, int out_size)
{
    const float* logits = (const float*)d_in[0];
    const int*   truth  = (const int*)  d_in[1];
    const float* weight = (const float*)d_in[2];
    float* out = (float*)d_out;

    const double T1 = 0.8, SM = 0.05;
    const double Cd = (double)C_CLS;
    const double y_on  = (1.0 - SM * Cd / (Cd - 1.0)) + SM / (Cd - 1.0);
    const double y_off = SM / (Cd - 1.0);
    auto logt1 = [](double v) { return (pow(v, 0.2) - 1.0) / 0.2; };
    auto Cy = [&](double y) {
        return y * logt1(y + 1e-10) - pow(y, 2.0 - T1) / (2.0 - T1);
    };
    const float A_on  = (float)(Cy(y_on)  + 5.0 * y_on);
    const float A_off = (float)(Cy(y_off) + 5.0 * y_off);
    const float B_on  = (float)(5.0 * y_on);
    const float B_off = (float)(5.0 * y_off);

    bitempered_row_kernel<<<NBLK, 256>>>(logits, truth, weight,
                                         A_off, B_off, A_on - A_off, B_on - B_off);
    bitempered_reduce_kernel<<<1, 1024>>>(weight, out);
}

// round 4
// speedup vs baseline: 2.3780x; 1.1600x over previous
#include <cuda_runtime.h>
#include <math.h>

#define B_ROWS 32768
#define C_CLS  1000
#define NBLK   (B_ROWS / 8)

__device__ float g_blk_loss[NBLK];

typedef unsigned long long u64;

__device__ __forceinline__ float frcp(float x) {
    float r; asm("rcp.approx.f32 %0, %1;" : "=f"(r) : "f"(x)); return r;
}
__device__ __forceinline__ float fpow_fast(float x, float p) {
    float lg; asm("lg2.approx.f32 %0, %1;" : "=f"(lg) : "f"(x));
    float e = lg * p;
    float r; asm("ex2.approx.f32 %0, %1;" : "=f"(r) : "f"(e)); return r;
}
__device__ __forceinline__ u64 pk(float x, float y) {
    u64 r; asm("mov.b64 %0, {%1,%2};" : "=l"(r) : "f"(x), "f"(y)); return r;
}
__device__ __forceinline__ void upk(u64 v, float& x, float& y) {
    asm("mov.b64 {%0,%1}, %2;" : "=f"(x), "=f"(y) : "l"(v));
}
__device__ __forceinline__ u64 fma2(u64 a, u64 b, u64 c) {
    u64 d; asm("fma.rn.f32x2 %0, %1, %2, %3;" : "=l"(d) : "l"(a), "l"(b), "l"(c)); return d;
}
__device__ __forceinline__ u64 mul2(u64 a, u64 b) {
    u64 d; asm("mul.rn.f32x2 %0, %1, %2;" : "=l"(d) : "l"(a), "l"(b)); return d;
}
__device__ __forceinline__ u64 add2(u64 a, u64 b) {
    u64 d; asm("add.rn.f32x2 %0, %1, %2;" : "=l"(d) : "l"(a), "l"(b)); return d;
}
__device__ __forceinline__ u64 rcp2(u64 v) {      // 2x MUFU
    float x, y; upk(v, x, y);
    return pk(frcp(x), frcp(y));
}

// ---------------------------------------------------------------------------
// Kernel 1: one warp per row; 32 elems/lane as 16 packed f32x2 regs.
//   u = -0.2*(x - mu) >= 0 (masked slots: u = +inf -> rcp -> 0)
//   5 passes: Z = sum (1 + u*s)^-5 ; first 4 update s = Z^-0.2
//   Reciprocals: pairs 0..5 via bit-seed + 2x Newton (FMA/ALU pipes),
//                pairs 6..15 via rcp.approx (MUFU). Balances pipe load.
//   zp = Zf^0.2 ; inv = 1/(u + zp) ; L = A_off - B_off*inv + (1/1.2)*inv^6
//   truth-class correction applied scalar on lane 0.
// ---------------------------------------------------------------------------
__global__ __launch_bounds__(256)
void bitempered_row_kernel(const float* __restrict__ logits,
                           const int*   __restrict__ truth,
                           const float* __restrict__ weight,
                           float A_off, float B_off, float dA, float dB)
{
    __shared__ float sm[8];
    const int lane = threadIdx.x & 31;
    const int wib  = threadIdx.x >> 5;
    const int row  = blockIdx.x * 8 + wib;

    const int   t  = truth[row];                       // uniform per warp
    const float xt = logits[(size_t)row * C_CLS + t];  // truth-class logit
    const float wt = __ldg(weight + t);

    const float4* xrow = (const float4*)(logits + (size_t)row * C_CLS);

    u64 u2[16];
    float xmax = -INFINITY;
    #pragma unroll
    for (int j = 0; j < 8; ++j) {
        const int q = lane + 32 * j;            // float4 index, valid iff q < 250
        float4 v;
        if (q < 250) v = xrow[q];
        else         v = make_float4(-INFINITY, -INFINITY, -INFINITY, -INFINITY);
        u2[2*j]   = pk(v.x, v.y);
        u2[2*j+1] = pk(v.z, v.w);
        xmax = fmaxf(xmax, fmaxf(fmaxf(v.x, v.y), fmaxf(v.z, v.w)));
    }
    #pragma unroll
    for (int o = 16; o; o >>= 1)
        xmax = fmaxf(xmax, __shfl_xor_sync(0xffffffffu, xmax, o));

    {
        const u64 cm = pk(-0.2f, -0.2f);
        const u64 ca = pk(0.2f * xmax, 0.2f * xmax);
        #pragma unroll
        for (int i = 0; i < 16; ++i)
            u2[i] = fma2(u2[i], cm, ca);        // masked raw -inf -> +inf
    }

    const u64 ONE2  = pk(1.0f, 1.0f);
    const u64 nONE2 = pk(-1.0f, -1.0f);
    const u64 TWO2  = pk(2.0f, 2.0f);

    // 4 fixed-point updates of s = Z^-0.2, then final Zf with converged s
    float s  = 1.0f;
    float zf = 0.0f;
    #pragma unroll
    for (int it = 0; it < 5; ++it) {
        const u64 s2  = pk(s, s);
        const u64 ns2 = pk(-s, -s);
        u64 z2 = pk(0.0f, 0.0f);
        // Newton pairs (always-valid classes; FMA + ALU pipes)
        #pragma unroll
        for (int i = 0; i < 6; ++i) {
            u64 nr2 = fma2(u2[i], ns2, nONE2);       // -(1 + u*s), in [-2.7,-1]
            float a, b; upk(nr2, a, b);
            float ya = __uint_as_float(0xFEF311C3u - __float_as_uint(a));
            float yb = __uint_as_float(0xFEF311C3u - __float_as_uint(b));
            u64 y = pk(ya, yb);                      // ~5% seed for 1/r
            y = mul2(y, fma2(nr2, y, TWO2));         // Newton 1  (~2.5e-3)
            y = mul2(y, fma2(nr2, y, TWO2));         // Newton 2  (~6e-6)
            u64 q2 = mul2(y, y);
            u64 q4 = mul2(q2, q2);
            z2 = fma2(q4, y, z2);                    // += r^-5
        }
        // MUFU pairs
        #pragma unroll
        for (int i = 6; i < 16; ++i) {
            u64 r2   = fma2(u2[i], s2, ONE2);        // >= 1 (inf for masked)
            u64 inv2 = rcp2(r2);                     // 0 for masked
            u64 q2   = mul2(inv2, inv2);
            u64 q4   = mul2(q2, q2);
            z2 = fma2(q4, inv2, z2);
        }
        float zx, zy; upk(z2, zx, zy);
        float z = zx + zy;
        #pragma unroll
        for (int o = 16; o; o >>= 1)
            z += __shfl_xor_sync(0xffffffffu, z, o);
        if (it < 4) s = fpow_fast(z, -0.2f);
        else        zf = z;
    }

    const float zp  = fpow_fast(zf, 0.2f);   // r_f = u + zp == 1 - 0.2*(x - nc)
    const u64   zp2 = pk(zp, zp);
    const u64   A2  = pk(A_off, A_off);
    const u64   nB2 = pk(-B_off, -B_off);
    const u64   C2  = pk(1.0f / 1.2f, 1.0f / 1.2f);

    const float4* w4 = (const float4*)weight;
    u64 acc2 = pk(0.0f, 0.0f);
    #pragma unroll
    for (int j = 0; j < 8; ++j) {
        const int q = lane + 32 * j;
        if (q < 250) {
            float4 wv = w4[q];
            u64 w2[2] = { pk(wv.x, wv.y), pk(wv.z, wv.w) };
            #pragma unroll
            for (int h = 0; h < 2; ++h) {
                u64 r2   = add2(u2[2*j + h], zp2);   // >= 1
                u64 inv2 = rcp2(r2);                 // = p^{0.2}
                u64 q2   = mul2(inv2, inv2);
                u64 q4   = mul2(q2, q2);
                u64 p12  = mul2(q4, q2);             // p^{1.2}
                u64 t2   = fma2(inv2, nB2, A2);      // A_off - B_off*inv
                u64 L2   = fma2(p12, C2, t2);
                acc2 = fma2(w2[h], L2, acc2);
            }
        }
    }
    float ax, ay; upk(acc2, ax, ay);
    float acc = ax + ay;
    #pragma unroll
    for (int o = 16; o; o >>= 1)
        acc += __shfl_xor_sync(0xffffffffu, acc, o);

    if (lane == 0) {
        const float ut   = fmaf(xt, -0.2f, 0.2f * xmax);
        const float invt = frcp(ut + zp);
        acc += wt * fmaf(-dB, invt, dA);
        sm[wib] = acc;
    }
    __syncthreads();
    if (threadIdx.x == 0) {
        float bs = 0.0f;
        #pragma unroll
        for (int i = 0; i < 8; ++i) bs += sm[i];
        g_blk_loss[blockIdx.x] = bs;
    }
}

// ---------------------------------------------------------------------------
// Kernel 2: reduce block partials + weight sum, write mean scalar.
// ---------------------------------------------------------------------------
__global__ __launch_bounds__(1024)
void bitempered_reduce_kernel(const float* __restrict__ weight,
                              float* __restrict__ out)
{
    __shared__ float sm[32];
    const int tid  = threadIdx.x;
    const int lane = tid & 31;
    const int w    = tid >> 5;

    float ws = (tid < C_CLS) ? weight[tid] : 0.0f;
    #pragma unroll
    for (int o = 16; o; o >>= 1) ws += __shfl_xor_sync(0xffffffffu, ws, o);
    if (lane == 0) sm[w] = ws;
    __syncthreads();
    float wsum = 0.0f;
    if (tid == 0) {
        #pragma unroll
        for (int i = 0; i < 32; ++i) wsum += sm[i];
    }
    __syncthreads();

    float ls = 0.0f;
    #pragma unroll
    for (int i = 0; i < NBLK / 1024; ++i) ls += g_blk_loss[tid + i * 1024];
    #pragma unroll
    for (int o = 16; o; o >>= 1) ls += __shfl_xor_sync(0xffffffffu, ls, o);
    if (lane == 0) sm[w] = ls;
    __syncthreads();
    if (tid == 0) {
        float lsum = 0.0f;
        #pragma unroll
        for (int i = 0; i < 32; ++i) lsum += sm[i];
        out[0] = lsum * ((float)C_CLS / wsum) * (1.0f / (float)B_ROWS);
    }
}

// ---------------------------------------------------------------------------
extern "C" void kernel_launch(void* const* d_in, const int* in_sizes, int n_in,
                              void* d_out, int out_size)
{
    const float* logits = (const float*)d_in[0];
    const int*   truth  = (const int*)  d_in[1];
    const float* weight = (const float*)d_in[2];
    float* out = (float*)d_out;

    const double T1 = 0.8, SM = 0.05;
    const double Cd = (double)C_CLS;
    const double y_on  = (1.0 - SM * Cd / (Cd - 1.0)) + SM / (Cd - 1.0);
    const double y_off = SM / (Cd - 1.0);
    auto logt1 = [](double v) { return (pow(v, 0.2) - 1.0) / 0.2; };
    auto Cy = [&](double y) {
        return y * logt1(y + 1e-10) - pow(y, 2.0 - T1) / (2.0 - T1);
    };
    const float A_on  = (float)(Cy(y_on)  + 5.0 * y_on);
    const float A_off = (float)(Cy(y_off) + 5.0 * y_off);
    const float B_on  = (float)(5.0 * y_on);
    const float B_off = (float)(5.0 * y_off);

    bitempered_row_kernel<<<NBLK, 256>>>(logits, truth, weight,
                                         A_off, B_off, A_on - A_off, B_on - B_off);
    bitempered_reduce_kernel<<<1, 1024>>>(weight, out);
}

// round 5
// speedup vs baseline: 3.0843x; 1.2970x over previous
#include <cuda_runtime.h>
#include <math.h>

#define B_ROWS 32768
#define C_CLS  1000
#define NBLK   (B_ROWS / 8)
#define N_UPDATES 3          // s-updates; total passes = N_UPDATES + 1
#define N_NEWTON  10         // pairs 0..9 via FMA-pipe Newton (mask-free region)

__device__ float g_blk_loss[NBLK];

typedef unsigned long long u64;

__device__ __forceinline__ float frcp(float x) {
    float r; asm("rcp.approx.f32 %0, %1;" : "=f"(r) : "f"(x)); return r;
}
__device__ __forceinline__ float fpow_fast(float x, float p) {
    float lg; asm("lg2.approx.f32 %0, %1;" : "=f"(lg) : "f"(x));
    float e = lg * p;
    float r; asm("ex2.approx.f32 %0, %1;" : "=f"(r) : "f"(e)); return r;
}
__device__ __forceinline__ u64 pk(float x, float y) {
    u64 r; asm("mov.b64 %0, {%1,%2};" : "=l"(r) : "f"(x), "f"(y)); return r;
}
__device__ __forceinline__ void upk(u64 v, float& x, float& y) {
    asm("mov.b64 {%0,%1}, %2;" : "=f"(x), "=f"(y) : "l"(v));
}
__device__ __forceinline__ u64 fma2(u64 a, u64 b, u64 c) {
    u64 d; asm("fma.rn.f32x2 %0, %1, %2, %3;" : "=l"(d) : "l"(a), "l"(b), "l"(c)); return d;
}
__device__ __forceinline__ u64 mul2(u64 a, u64 b) {
    u64 d; asm("mul.rn.f32x2 %0, %1, %2;" : "=l"(d) : "l"(a), "l"(b)); return d;
}
__device__ __forceinline__ u64 rcp2(u64 v) {      // 2x MUFU
    float x, y; upk(v, x, y);
    return pk(frcp(x), frcp(y));
}

// ---------------------------------------------------------------------------
// Kernel 1: one warp per row; 32 elems/lane as 16 packed f32x2 regs.
//   u = -0.2*(x - mu) >= 0 (masked slots: u = +inf -> rcp -> 0)
//   4 passes: Z = sum (1 + u*s)^-5 ; first 3 update s = Z^-0.2.
//   Final pass keeps inv = 1/(1+u*s) per element (overwrites u2).
//   zp = Zf^0.2, s_f = 1/zp; loss uses inv_f = s_f*inv ~= 1/(u+zp):
//   L = A_off - B_off*inv_f + (1/1.2)*inv_f^6 ; truth fix scalar on lane 0.
//   Reciprocals: pairs 0..9 via packed 64-bit seed + 2x Newton (FMA/ALU),
//                pairs 10..15 via rcp.approx (MUFU, inf-safe for masked).
// ---------------------------------------------------------------------------
__global__ __launch_bounds__(256)
void bitempered_row_kernel(const float* __restrict__ logits,
                           const int*   __restrict__ truth,
                           const float* __restrict__ weight,
                           float A_off, float B_off, float dA, float dB)
{
    __shared__ float sm[8];
    const int lane = threadIdx.x & 31;
    const int wib  = threadIdx.x >> 5;
    const int row  = blockIdx.x * 8 + wib;

    const int   t  = truth[row];                       // uniform per warp
    const float xt = logits[(size_t)row * C_CLS + t];  // truth-class logit
    const float wt = __ldg(weight + t);

    const float4* xrow = (const float4*)(logits + (size_t)row * C_CLS);

    u64 u2[16];
    float xmax = -INFINITY;
    #pragma unroll
    for (int j = 0; j < 8; ++j) {
        const int q = lane + 32 * j;            // float4 index, valid iff q < 250
        float4 v;
        if (q < 250) v = xrow[q];
        else         v = make_float4(-INFINITY, -INFINITY, -INFINITY, -INFINITY);
        u2[2*j]   = pk(v.x, v.y);
        u2[2*j+1] = pk(v.z, v.w);
        xmax = fmaxf(xmax, fmaxf(fmaxf(v.x, v.y), fmaxf(v.z, v.w)));
    }
    #pragma unroll
    for (int o = 16; o; o >>= 1)
        xmax = fmaxf(xmax, __shfl_xor_sync(0xffffffffu, xmax, o));

    {
        const u64 cm = pk(-0.2f, -0.2f);
        const u64 ca = pk(0.2f * xmax, 0.2f * xmax);
        #pragma unroll
        for (int i = 0; i < 16; ++i)
            u2[i] = fma2(u2[i], cm, ca);        // masked raw -inf -> +inf
    }

    const u64 ONE2   = pk(1.0f, 1.0f);
    const u64 nONE2  = pk(-1.0f, -1.0f);
    const u64 TWO2   = pk(2.0f, 2.0f);
    const u64 MAGIC2 = 0xFEF311C3FEF311C3ULL;   // packed rcp seed (no borrow:
                                                // low field >= bits(nr), nr in [-inf,-1])

    // N_UPDATES updates of s = Z^-0.2, then final pass stores inv, sums Zf
    float s  = 1.0f;
    float zf = 0.0f;
    #pragma unroll
    for (int it = 0; it <= N_UPDATES; ++it) {
        const u64 s2  = pk(s, s);
        const u64 ns2 = pk(-s, -s);
        u64 z2 = pk(0.0f, 0.0f);
        // Newton pairs (mask-free classes; FMA + ALU pipes only)
        #pragma unroll
        for (int i = 0; i < N_NEWTON; ++i) {
            u64 nr2 = fma2(u2[i], ns2, nONE2);   // -(1 + u*s), in [-3,-1]
            u64 y   = MAGIC2 - nr2;              // ~5% packed seed for 1/r
            y = mul2(y, fma2(nr2, y, TWO2));     // Newton 1 (~2.5e-3)
            y = mul2(y, fma2(nr2, y, TWO2));     // Newton 2 (~6e-6)
            if (it == N_UPDATES) u2[i] = y;      // keep inv for fused loss
            u64 q2 = mul2(y, y);
            u64 q4 = mul2(q2, q2);
            z2 = fma2(q4, y, z2);                // += r^-5
        }
        // MUFU pairs (inf-safe for masked elements)
        #pragma unroll
        for (int i = N_NEWTON; i < 16; ++i) {
            u64 r2   = fma2(u2[i], s2, ONE2);    // >= 1 (inf for masked)
            u64 inv2 = rcp2(r2);                 // 0 for masked
            if (it == N_UPDATES) u2[i] = inv2;
            u64 q2   = mul2(inv2, inv2);
            u64 q4   = mul2(q2, q2);
            z2 = fma2(q4, inv2, z2);
        }
        float zx, zy; upk(z2, zx, zy);
        float z = zx + zy;
        #pragma unroll
        for (int o = 16; o; o >>= 1)
            z += __shfl_xor_sync(0xffffffffu, z, o);
        if (it < N_UPDATES) s = fpow_fast(z, -0.2f);
        else                zf = z;
    }

    const float zp  = fpow_fast(zf, 0.2f);   // r_f = u + zp
    const float sf  = frcp(zp);              // 1/(u+zp) ~= sf * inv
    const u64   sf2 = pk(sf, sf);
    const u64   A2  = pk(A_off, A_off);
    const u64   nB2 = pk(-B_off, -B_off);
    const u64   C2  = pk(1.0f / 1.2f, 1.0f / 1.2f);

    const float4* w4 = (const float4*)weight;
    u64 acc2 = pk(0.0f, 0.0f);
    #pragma unroll
    for (int j = 0; j < 8; ++j) {
        const int q = lane + 32 * j;
        if (q < 250) {
            float4 wv = w4[q];
            u64 w2[2] = { pk(wv.x, wv.y), pk(wv.z, wv.w) };
            #pragma unroll
            for (int h = 0; h < 2; ++h) {
                u64 m   = mul2(u2[2*j + h], sf2);  // inv_f = p^{0.2}
                u64 q2  = mul2(m, m);
                u64 q4  = mul2(q2, q2);
                u64 p12 = mul2(q4, q2);            // p^{1.2}
                u64 t2  = fma2(m, nB2, A2);        // A_off - B_off*inv_f
                u64 L2  = fma2(p12, C2, t2);
                acc2 = fma2(w2[h], L2, acc2);
            }
        }
    }
    float ax, ay; upk(acc2, ax, ay);
    float acc = ax + ay;
    #pragma unroll
    for (int o = 16; o; o >>= 1)
        acc += __shfl_xor_sync(0xffffffffu, acc, o);

    if (lane == 0) {
        const float ut   = fmaf(xt, -0.2f, 0.2f * xmax);
        const float invt = frcp(ut + zp);
        acc += wt * fmaf(-dB, invt, dA);
        sm[wib] = acc;
    }
    __syncthreads();
    if (threadIdx.x == 0) {
        float bs = 0.0f;
        #pragma unroll
        for (int i = 0; i < 8; ++i) bs += sm[i];
        g_blk_loss[blockIdx.x] = bs;
    }
}

// ---------------------------------------------------------------------------
// Kernel 2: reduce block partials + weight sum, write mean scalar.
// ---------------------------------------------------------------------------
__global__ __launch_bounds__(1024)
void bitempered_reduce_kernel(const float* __restrict__ weight,
                              float* __restrict__ out)
{
    __shared__ float sm[32];
    const int tid  = threadIdx.x;
    const int lane = tid & 31;
    const int w    = tid >> 5;

    float ws = (tid < C_CLS) ? weight[tid] : 0.0f;
    #pragma unroll
    for (int o = 16; o; o >>= 1) ws += __shfl_xor_sync(0xffffffffu, ws, o);
    if (lane == 0) sm[w] = ws;
    __syncthreads();
    float wsum = 0.0f;
    if (tid == 0) {
        #pragma unroll
        for (int i = 0; i < 32; ++i) wsum += sm[i];
    }
    __syncthreads();

    float ls = 0.0f;
    #pragma unroll
    for (int i = 0; i < NBLK / 1024; ++i) ls += g_blk_loss[tid + i * 1024];
    #pragma unroll
    for (int o = 16; o; o >>= 1) ls += __shfl_xor_sync(0xffffffffu, ls, o);
    if (lane == 0) sm[w] = ls;
    __syncthreads();
    if (tid == 0) {
        float lsum = 0.0f;
        #pragma unroll
        for (int i = 0; i < 32; ++i) lsum += sm[i];
        out[0] = lsum * ((float)C_CLS / wsum) * (1.0f / (float)B_ROWS);
    }
}

// ---------------------------------------------------------------------------
extern "C" void kernel_launch(void* const* d_in, const int* in_sizes, int n_in,
                              void* d_out, int out_size)
{
    const float* logits = (const float*)d_in[0];
    const int*   truth  = (const int*)  d_in[1];
    const float* weight = (const float*)d_in[2];
    float* out = (float*)d_out;

    const double T1 = 0.8, SM = 0.05;
    const double Cd = (double)C_CLS;
    const double y_on  = (1.0 - SM * Cd / (Cd - 1.0)) + SM / (Cd - 1.0);
    const double y_off = SM / (Cd - 1.0);
    auto logt1 = [](double v) { return (pow(v, 0.2) - 1.0) / 0.2; };
    auto Cy = [&](double y) {
        return y * logt1(y + 1e-10) - pow(y, 2.0 - T1) / (2.0 - T1);
    };
    const float A_on  = (float)(Cy(y_on)  + 5.0 * y_on);
    const float A_off = (float)(Cy(y_off) + 5.0 * y_off);
    const float B_on  = (float)(5.0 * y_on);
    const float B_off = (float)(5.0 * y_off);

    bitempered_row_kernel<<<NBLK, 256>>>(logits, truth, weight,
                                         A_off, B_off, A_on - A_off, B_on - B_off);
    bitempered_reduce_kernel<<<1, 1024>>>(weight, out);
}